// round 5
// baseline (speedup 1.0000x reference)
#include <cuda_runtime.h>

#define BB 32
#define HH 512
#define WW 512
#define FINF __int_as_float(0x7f800000)

// scratch for horizontal-pass result (dark-channel row-eroded), [B,H,W]
__device__ float g_scratch[BB * HH * WW];

// ---------------------------------------------------------------------------
// Pass 1: channel-min (3 channels) + horizontal 15-tap min, +inf padding.
// Block = 256 threads = 4 rows x 64 threads; each thread -> 8 consecutive x.
// Register window w[0..23] covers x in [x0-8, x0+15]; window for output j
// (x = x0+j) is w[j+1 .. j+15]. Doubling: m2, m4, m8; out = min(m8[j+1], m8[j+8]).
// ---------------------------------------------------------------------------
__global__ __launch_bounds__(256) void hpass_kernel(const float* __restrict__ I,
                                                    float* __restrict__ S) {
    const int tid = threadIdx.x;
    const int row = blockIdx.x * 4 + (tid >> 6);   // global row in [0, B*H)
    const int t   = tid & 63;
    const int x0  = t << 3;

    const int b = row >> 9;          // row / 512
    const int y = row & 511;         // row % 512
    const float* r0 = I + ((size_t)b * 3) * (HH * WW) + (size_t)y * WW;
    const float* r1 = r0 + HH * WW;
    const float* r2 = r0 + 2 * HH * WW;

    float w[24];
#pragma unroll
    for (int i = 0; i < 6; i++) {
        const int xb = x0 - 8 + i * 4;
        const bool valid = (xb >= 0) && (xb < WW);
        float4 a = make_float4(FINF, FINF, FINF, FINF);
        float4 c = make_float4(FINF, FINF, FINF, FINF);
        float4 d = make_float4(FINF, FINF, FINF, FINF);
        if (valid) {
            a = *reinterpret_cast<const float4*>(r0 + xb);
            c = *reinterpret_cast<const float4*>(r1 + xb);
            d = *reinterpret_cast<const float4*>(r2 + xb);
        }
        w[i * 4 + 0] = fminf(fminf(a.x, c.x), d.x);
        w[i * 4 + 1] = fminf(fminf(a.y, c.y), d.y);
        w[i * 4 + 2] = fminf(fminf(a.z, c.z), d.z);
        w[i * 4 + 3] = fminf(fminf(a.w, c.w), d.w);
    }

    // doubling: m2[i] = min(w[i], w[i+1]); m4[i] = min(m2[i], m2[i+2]);
    // m8[i] = min(m4[i], m4[i+4]) covers w[i..i+7]
    float m2[22];
#pragma unroll
    for (int i = 1; i <= 21; i++) m2[i] = fminf(w[i], w[i + 1]);
    float m4[20];
#pragma unroll
    for (int i = 1; i <= 19; i++) m4[i] = fminf(m2[i], m2[i + 2]);
    float m8[16];
#pragma unroll
    for (int i = 1; i <= 15; i++) m8[i] = fminf(m4[i], m4[i + 4]);

    float o[8];
#pragma unroll
    for (int j = 0; j < 8; j++) o[j] = fminf(m8[j + 1], m8[j + 8]);

    float* sp = S + (size_t)row * WW + x0;
    *reinterpret_cast<float4*>(sp)     = make_float4(o[0], o[1], o[2], o[3]);
    *reinterpret_cast<float4*>(sp + 4) = make_float4(o[4], o[5], o[6], o[7]);
}

// ---------------------------------------------------------------------------
// Pass 2: vertical 15-tap min over scratch, +inf padding.
// Thread = one column x, 8 output rows [y0, y0+8). Loads rows y0-7..y0+14
// (22 coalesced loads). Window for output j = w[j .. j+14];
// out = min(m8[j], m8[j+7]).
// ---------------------------------------------------------------------------
__global__ __launch_bounds__(256) void vpass_kernel(const float* __restrict__ S,
                                                    float* __restrict__ O) {
    const int x  = blockIdx.x * blockDim.x + threadIdx.x;   // 0..511
    const int y0 = blockIdx.y << 3;
    const int b  = blockIdx.z;

    const float* col = S + (size_t)b * HH * WW + x;

    float w[22];
#pragma unroll
    for (int i = 0; i < 22; i++) {
        const int yy = y0 - 7 + i;
        float v = FINF;
        if (yy >= 0 && yy < HH) v = __ldg(col + (size_t)yy * WW);
        w[i] = v;
    }

    float m2[21];
#pragma unroll
    for (int i = 0; i <= 20; i++) m2[i] = fminf(w[i], w[i + 1]);
    float m4[19];
#pragma unroll
    for (int i = 0; i <= 18; i++) m4[i] = fminf(m2[i], m2[i + 2]);
    float m8[15];
#pragma unroll
    for (int i = 0; i <= 14; i++) m8[i] = fminf(m4[i], m4[i + 4]);

    float* op = O + ((size_t)b * HH + y0) * WW + x;
#pragma unroll
    for (int j = 0; j < 8; j++) {
        op[(size_t)j * WW] = fminf(m8[j], m8[j + 7]);
    }
}

extern "C" void kernel_launch(void* const* d_in, const int* in_sizes, int n_in,
                              void* d_out, int out_size) {
    // Find I by element count (robust to metadata ordering; k=15 is baked in).
    const float* I = (const float*)d_in[0];
    for (int i = 0; i < n_in; i++) {
        if (in_sizes[i] == BB * 3 * HH * WW) I = (const float*)d_in[i];
    }
    float* out = (float*)d_out;

    float* scratch = nullptr;
    cudaGetSymbolAddress((void**)&scratch, g_scratch);

    // Pass 1: B*H = 16384 rows, 4 rows/block
    dim3 hgrid((BB * HH) / 4);
    hpass_kernel<<<hgrid, 256>>>(I, scratch);

    // Pass 2: x-tiles x y-chunks x batch
    dim3 vgrid(WW / 256, HH / 8, BB);
    vpass_kernel<<<vgrid, 256>>>(scratch, out);
}